// round 2
// baseline (speedup 1.0000x reference)
#include <cuda_runtime.h>
#include <math_constants.h>
#include <cstdint>

// Problem dims
#define T_STEPS 256
#define BATCH   128
#define FDIM    1024
#define UDIM    512
#define GDIM    2048   // 4*U, gate order i,f,g,o
#define NCODES  1024

// ---------------- scratch (device globals: allowed; no runtime allocs) ----------
__device__ float g_xz[(size_t)T_STEPS * BATCH * GDIM];     // 256 MB: x@W_in + b
__device__ float g_h[2][BATCH * UDIM];                     // double-buffered h
__device__ float g_c[BATCH * UDIM];
__device__ float g_hseq[(size_t)T_STEPS * BATCH * UDIM];   // masked h sequence
__device__ unsigned int g_bar_count;
__device__ unsigned int g_bar_gen;

// ---------------- grid-wide barrier (blocks must be co-resident) ----------------
__device__ __forceinline__ void grid_barrier(unsigned nb) {
    __syncthreads();
    if (threadIdx.x == 0) {
        __threadfence();                                   // release my step's stores
        volatile unsigned int* genp = &g_bar_gen;
        unsigned my = *genp;
        __threadfence();
        if (atomicAdd(&g_bar_count, 1u) == nb - 1u) {
            g_bar_count = 0u;                              // only last writer touches it
            __threadfence();
            atomicAdd(&g_bar_gen, 1u);
        } else {
            int spins = 0;
            while (*genp == my) {
                if (++spins > 32) __nanosleep(128);
            }
        }
        __threadfence();                                   // acquire others' stores
    }
    __syncthreads();
}

// ---------------- init: zero h (both buffers) and c --------------------------------
__global__ void init_state() {
    int i = blockIdx.x * blockDim.x + threadIdx.x;
    if (i < BATCH * UDIM) {
        g_h[0][i] = 0.f;
        g_h[1][i] = 0.f;
        g_c[i]    = 0.f;
    }
    if (i == 0) { g_bar_count = 0u; g_bar_gen = 0u; }
}

// ---------------- generic tiled SGEMM: C = [relu](A*B + bias) ----------------------
// A: [M,K] row-major, B: [K,N] row-major, bias: [N]. BM=BN=128, BK=16, 256 thr, 8x8.
template <bool RELU>
__global__ void __launch_bounds__(256) sgemm_bias(
    const float* __restrict__ A, const float* __restrict__ B,
    const float* __restrict__ bias, float* __restrict__ C,
    int M, int N, int K)
{
    __shared__ float As[16][132];   // transposed A tile, padded
    __shared__ float Bs[16][128];

    const int tid  = threadIdx.x;
    const int tx   = tid & 15;      // col group
    const int ty   = tid >> 4;      // row group
    const int brow = blockIdx.y * 128;
    const int bcol = blockIdx.x * 128;

    const int aRow = tid >> 2, aC4 = tid & 3;    // A loader: 64 rows/pass x 4 float4 cols
    const int bRow = tid >> 5, bC4 = tid & 31;   // B loader: 8 rows/pass x 32 float4 cols

    float acc[8][8];
#pragma unroll
    for (int i = 0; i < 8; ++i)
#pragma unroll
        for (int j = 0; j < 8; ++j) acc[i][j] = 0.f;

    for (int k0 = 0; k0 < K; k0 += 16) {
#pragma unroll
        for (int p = 0; p < 2; ++p) {
            int r = aRow + p * 64;
            float4 v = *(const float4*)&A[(size_t)(brow + r) * K + k0 + aC4 * 4];
            As[aC4 * 4 + 0][r] = v.x;
            As[aC4 * 4 + 1][r] = v.y;
            As[aC4 * 4 + 2][r] = v.z;
            As[aC4 * 4 + 3][r] = v.w;
        }
#pragma unroll
        for (int p = 0; p < 2; ++p) {
            int r = bRow + p * 8;
            *(float4*)&Bs[r][bC4 * 4] =
                *(const float4*)&B[(size_t)(k0 + r) * N + bcol + bC4 * 4];
        }
        __syncthreads();
#pragma unroll
        for (int k = 0; k < 16; ++k) {
            float a[8], b[8];
            *(float4*)&a[0] = *(const float4*)&As[k][ty * 8];
            *(float4*)&a[4] = *(const float4*)&As[k][ty * 8 + 4];
            *(float4*)&b[0] = *(const float4*)&Bs[k][tx * 8];
            *(float4*)&b[4] = *(const float4*)&Bs[k][tx * 8 + 4];
#pragma unroll
            for (int i = 0; i < 8; ++i)
#pragma unroll
                for (int j = 0; j < 8; ++j)
                    acc[i][j] = fmaf(a[i], b[j], acc[i][j]);
        }
        __syncthreads();
    }

#pragma unroll
    for (int i = 0; i < 8; ++i) {
        int row = brow + ty * 8 + i;
#pragma unroll
        for (int j = 0; j < 8; j += 4) {
            int col = bcol + tx * 8 + j;
            float4 v;
            v.x = acc[i][j + 0] + bias[col + 0];
            v.y = acc[i][j + 1] + bias[col + 1];
            v.z = acc[i][j + 2] + bias[col + 2];
            v.w = acc[i][j + 3] + bias[col + 3];
            if (RELU) {
                v.x = fmaxf(v.x, 0.f); v.y = fmaxf(v.y, 0.f);
                v.z = fmaxf(v.z, 0.f); v.w = fmaxf(v.w, 0.f);
            }
            *(float4*)&C[(size_t)row * N + col] = v;
        }
    }
}

// ---------------- persistent LSTM recurrence --------------------------------------
// 128 blocks x 256 threads. Block bid owns 4 units (ub..ub+3) -> 16 z-cols
// (4 gates x 4 units), all 128 batch rows. Thread (cx,ry): col cx (0..15),
// rows ry*8..ry*8+7.
#define NRB 128
__global__ void __launch_bounds__(256, 1) lstm_rec_kernel(
    const float* __restrict__ Wrec, const float* __restrict__ blstm,
    const float* __restrict__ mask)
{
    const int tid  = threadIdx.x;
    const int bid  = blockIdx.x;
    const int ub   = bid * 4;
    const int cx   = tid & 15;
    const int ry   = tid >> 4;
    const int gate = cx >> 2;
    const int uu   = cx & 3;
    const int col  = gate * UDIM + ub + uu;

    __shared__ float hs[64][132];   // transposed h tile: hs[k][row]
    __shared__ float ws[64][16];    // W_rec tile for our 16 cols
    __shared__ float zz[16][128];   // z exchange: zz[c][row]

    const float bias = blstm[col];

    for (int t = 0; t < T_STEPS; ++t) {
        const float* hin  = g_h[t & 1];
        float*       hout = g_h[(t + 1) & 1];

        float acc[8];
#pragma unroll
        for (int r = 0; r < 8; ++r) acc[r] = 0.f;

        for (int k0 = 0; k0 < UDIM; k0 += 64) {
            // stage h (all 128 rows x 64 k), transposed. L2 loads (cross-SM coherence).
#pragma unroll
            for (int i = 0; i < 8; ++i) {
                int idx = tid + 256 * i;        // 0..2047 float4 slots
                int row = idx >> 4;
                int k4  = idx & 15;
                float4 v = __ldcg((const float4*)(hin + row * UDIM + k0 + k4 * 4));
                hs[k4 * 4 + 0][row] = v.x;
                hs[k4 * 4 + 1][row] = v.y;
                hs[k4 * 4 + 2][row] = v.z;
                hs[k4 * 4 + 3][row] = v.w;
            }
            // stage W_rec tile
#pragma unroll
            for (int i = 0; i < 4; ++i) {
                int idx = tid + 256 * i;        // 0..1023
                int k = idx >> 4;
                int c = idx & 15;
                int cc = (c >> 2) * UDIM + ub + (c & 3);
                ws[k][c] = Wrec[(size_t)(k0 + k) * GDIM + cc];
            }
            __syncthreads();
#pragma unroll
            for (int k = 0; k < 64; ++k) {
                float w = ws[k][cx];
                float4 h0 = *(const float4*)&hs[k][ry * 8];
                float4 h1 = *(const float4*)&hs[k][ry * 8 + 4];
                acc[0] = fmaf(h0.x, w, acc[0]);
                acc[1] = fmaf(h0.y, w, acc[1]);
                acc[2] = fmaf(h0.z, w, acc[2]);
                acc[3] = fmaf(h0.w, w, acc[3]);
                acc[4] = fmaf(h1.x, w, acc[4]);
                acc[5] = fmaf(h1.y, w, acc[5]);
                acc[6] = fmaf(h1.z, w, acc[6]);
                acc[7] = fmaf(h1.w, w, acc[7]);
            }
            __syncthreads();
        }

        // stage xz for our 16 columns (semi-coalesced), then add recurrent part
#pragma unroll
        for (int i = 0; i < 8; ++i) {
            int idx = tid + 256 * i;            // 0..2047
            int row = idx >> 4;
            int c   = idx & 15;
            int cc  = (c >> 2) * UDIM + ub + (c & 3);
            zz[c][row] = g_xz[((size_t)t * BATCH + row) * GDIM + cc];
        }
        __syncthreads();
#pragma unroll
        for (int r = 0; r < 8; ++r)
            zz[cx][ry * 8 + r] += acc[r] + bias;
        __syncthreads();

        // gate math + state update: 64 threads (cx<4), each: 1 unit x 8 rows
        if (cx < 4) {
            int u = ub + cx;
#pragma unroll
            for (int r = 0; r < 8; ++r) {
                int row = ry * 8 + r;
                float zi = zz[cx][row];
                float zf = zz[4 + cx][row];
                float zg = zz[8 + cx][row];
                float zo = zz[12 + cx][row];
                float ig = 1.f / (1.f + __expf(-zi));
                float fg = 1.f / (1.f + __expf(-zf));
                float gg = tanhf(zg);
                float og = 1.f / (1.f + __expf(-zo));
                float cc = fg * __ldcg(&g_c[row * UDIM + u]) + ig * gg;
                __stcg(&g_c[row * UDIM + u], cc);
                float h = og * tanhf(cc);
                __stcg(&hout[row * UDIM + u], h);
                float m = __ldg(&mask[t * BATCH + row]);
                __stcg(&g_hseq[((size_t)t * BATCH + row) * UDIM + u], h * m);
            }
        }
        grid_barrier(NRB);
    }
}

// ---------------- row softmax in place (1024 cols, 1 block/row) -------------------
__global__ void __launch_bounds__(256) softmax_kernel(float* __restrict__ out) {
    const int row = blockIdx.x;
    float* p = out + (size_t)row * NCODES;
    const int tid = threadIdx.x;

    float4 v = *(float4*)(p + tid * 4);

    __shared__ float warpred[8];
    __shared__ float bcast;

    float m = fmaxf(fmaxf(v.x, v.y), fmaxf(v.z, v.w));
#pragma unroll
    for (int o = 16; o > 0; o >>= 1) m = fmaxf(m, __shfl_xor_sync(0xffffffffu, m, o));
    if ((tid & 31) == 0) warpred[tid >> 5] = m;
    __syncthreads();
    if (tid == 0) {
        float mm = warpred[0];
#pragma unroll
        for (int i = 1; i < 8; ++i) mm = fmaxf(mm, warpred[i]);
        bcast = mm;
    }
    __syncthreads();
    const float M = bcast;

    float4 e;
    e.x = __expf(v.x - M);
    e.y = __expf(v.y - M);
    e.z = __expf(v.z - M);
    e.w = __expf(v.w - M);
    float s = e.x + e.y + e.z + e.w;
#pragma unroll
    for (int o = 16; o > 0; o >>= 1) s += __shfl_xor_sync(0xffffffffu, s, o);
    if ((tid & 31) == 0) warpred[tid >> 5] = s;
    __syncthreads();
    if (tid == 0) {
        float ss = warpred[0];
#pragma unroll
        for (int i = 1; i < 8; ++i) ss += warpred[i];
        bcast = ss;
    }
    __syncthreads();
    const float inv = 1.f / bcast;

    e.x *= inv; e.y *= inv; e.z *= inv; e.w *= inv;
    *(float4*)(p + tid * 4) = e;
}

// ---------------- launch ----------------------------------------------------------
extern "C" void kernel_launch(void* const* d_in, const int* in_sizes, int n_in,
                              void* d_out, int out_size) {
    const float* x       = (const float*)d_in[0];  // [T,B,F]
    const float* mask    = (const float*)d_in[1];  // [T,B]
    const float* W_in    = (const float*)d_in[2];  // [F,4U]
    const float* W_rec   = (const float*)d_in[3];  // [U,4U]
    const float* b_lstm  = (const float*)d_in[4];  // [4U]
    const float* W_dense = (const float*)d_in[5];  // [U,CODES]
    const float* b_dense = (const float*)d_in[6];  // [CODES]
    float* out = (float*)d_out;                    // [T,B,CODES]

    float* xz   = nullptr;
    float* hseq = nullptr;
    cudaGetSymbolAddress((void**)&xz, g_xz);
    cudaGetSymbolAddress((void**)&hseq, g_hseq);

    // 1) xz = x @ W_in + b_lstm   (M=32768, N=2048, K=1024)
    {
        dim3 grid(GDIM / 128, (T_STEPS * BATCH) / 128);
        sgemm_bias<false><<<grid, 256>>>(x, W_in, b_lstm, xz,
                                         T_STEPS * BATCH, GDIM, FDIM);
    }

    // 2) zero h/c state + barrier counters
    init_state<<<(BATCH * UDIM + 255) / 256, 256>>>();

    // 3) persistent recurrence over all 256 timesteps
    lstm_rec_kernel<<<NRB, 256>>>(W_rec, b_lstm, mask);

    // 4) logits = relu(masked_hseq @ W_dense + b_dense)  (M=32768, N=1024, K=512)
    {
        dim3 grid(NCODES / 128, (T_STEPS * BATCH) / 128);
        sgemm_bias<true><<<grid, 256>>>(hseq, W_dense, b_dense, out,
                                        T_STEPS * BATCH, NCODES, UDIM);
    }

    // 5) softmax rows in place
    softmax_kernel<<<T_STEPS * BATCH, 256>>>(out);
}

// round 5
// speedup vs baseline: 1.5151x; 1.5151x over previous
#include <cuda_runtime.h>
#include <math_constants.h>
#include <cstdint>

// Problem dims
#define T_STEPS 256
#define BATCH   128
#define FDIM    1024
#define UDIM    512
#define GDIM    2048   // 4*U, gate order i,f,g,o
#define NCODES  1024

// ---------------- scratch (device globals; no runtime allocs) ---------------------
__device__ float g_xz[(size_t)T_STEPS * BATCH * GDIM];     // 256 MB: x@W_in + b
__device__ float g_h[2][BATCH * UDIM];                     // double-buffered h
__device__ float g_c[BATCH * UDIM];                        // cell state
__device__ float g_hseq[(size_t)T_STEPS * BATCH * UDIM];   // masked h sequence
__device__ float g_wpack[UDIM * GDIM];                     // packed W_rec: [32][512][64]

// ---------------- init: zero h buffers + c ----------------------------------------
__global__ void init_state() {
    int i = blockIdx.x * blockDim.x + threadIdx.x;
    if (i < BATCH * UDIM) {
        g_h[0][i] = 0.f;
        g_h[1][i] = 0.f;
        g_c[i]    = 0.f;
    }
}

// ---------------- pack W_rec: wpack[ug*32768 + k*64 + u*4 + gate] ------------------
// = W_rec[k][gate*512 + ug*16 + u]. Makes per-step staging a coalesced float4 copy.
__global__ void pack_wrec(const float* __restrict__ Wrec) {
    int idx = blockIdx.x * blockDim.x + threadIdx.x;   // 0 .. 512*2048-1
    if (idx < UDIM * GDIM) {
        int ug   = idx >> 15;          // /32768
        int rem  = idx & 32767;
        int k    = rem >> 6;
        int c    = rem & 63;           // u*4 + gate
        int gate = c & 3;
        int u    = c >> 2;
        g_wpack[idx] = Wrec[(size_t)k * GDIM + gate * UDIM + ug * 16 + u];
    }
}

// ---------------- generic tiled SGEMM: C = [relu](A*B + bias) ---------------------
// A: [M,K] row-major, B: [K,N] row-major, bias: [N]. BM=BN=128, BK=16, 256 thr, 8x8.
template <bool RELU>
__global__ void __launch_bounds__(256) sgemm_bias(
    const float* __restrict__ A, const float* __restrict__ B,
    const float* __restrict__ bias, float* __restrict__ C,
    int M, int N, int K)
{
    __shared__ float As[16][132];   // transposed A tile, padded
    __shared__ float Bs[16][128];

    const int tid  = threadIdx.x;
    const int tx   = tid & 15;      // col group
    const int ty   = tid >> 4;      // row group
    const int brow = blockIdx.y * 128;
    const int bcol = blockIdx.x * 128;

    const int aRow = tid >> 2, aC4 = tid & 3;    // A loader: 64 rows/pass x 4 float4 cols
    const int bRow = tid >> 5, bC4 = tid & 31;   // B loader: 8 rows/pass x 32 float4 cols

    float acc[8][8];
#pragma unroll
    for (int i = 0; i < 8; ++i)
#pragma unroll
        for (int j = 0; j < 8; ++j) acc[i][j] = 0.f;

    for (int k0 = 0; k0 < K; k0 += 16) {
#pragma unroll
        for (int p = 0; p < 2; ++p) {
            int r = aRow + p * 64;
            float4 v = *(const float4*)&A[(size_t)(brow + r) * K + k0 + aC4 * 4];
            As[aC4 * 4 + 0][r] = v.x;
            As[aC4 * 4 + 1][r] = v.y;
            As[aC4 * 4 + 2][r] = v.z;
            As[aC4 * 4 + 3][r] = v.w;
        }
#pragma unroll
        for (int p = 0; p < 2; ++p) {
            int r = bRow + p * 8;
            *(float4*)&Bs[r][bC4 * 4] =
                *(const float4*)&B[(size_t)(k0 + r) * N + bcol + bC4 * 4];
        }
        __syncthreads();
#pragma unroll
        for (int k = 0; k < 16; ++k) {
            float a[8], b[8];
            *(float4*)&a[0] = *(const float4*)&As[k][ty * 8];
            *(float4*)&a[4] = *(const float4*)&As[k][ty * 8 + 4];
            *(float4*)&b[0] = *(const float4*)&Bs[k][tx * 8];
            *(float4*)&b[4] = *(const float4*)&Bs[k][tx * 8 + 4];
#pragma unroll
            for (int i = 0; i < 8; ++i)
#pragma unroll
                for (int j = 0; j < 8; ++j)
                    acc[i][j] = fmaf(a[i], b[j], acc[i][j]);
        }
        __syncthreads();
    }

#pragma unroll
    for (int i = 0; i < 8; ++i) {
        int row = brow + ty * 8 + i;
#pragma unroll
        for (int j = 0; j < 8; j += 4) {
            int col = bcol + tx * 8 + j;
            float4 v;
            v.x = acc[i][j + 0] + bias[col + 0];
            v.y = acc[i][j + 1] + bias[col + 1];
            v.z = acc[i][j + 2] + bias[col + 2];
            v.w = acc[i][j + 3] + bias[col + 3];
            if (RELU) {
                v.x = fmaxf(v.x, 0.f); v.y = fmaxf(v.y, 0.f);
                v.z = fmaxf(v.z, 0.f); v.w = fmaxf(v.w, 0.f);
            }
            *(float4*)&C[(size_t)row * N + col] = v;
        }
    }
}

// ---------------- per-timestep LSTM step kernel ------------------------------------
// 128 blocks x 256 threads. bid -> unit group (bid>>2, 16 units) x batch group
// (bid&3, 32 rows). No persistence, no device barrier: one launch per timestep.
#define HS_PITCH 516   // 512 + 4 pad

__global__ void __launch_bounds__(256) lstm_step_kernel(
    int t, const float* __restrict__ blstm, const float* __restrict__ mask)
{
    extern __shared__ float smem[];
    float* ws = smem;                         // [512][64]: ws[k][u_local*4+gate]
    float* hs = smem + 512 * 64;              // [32][HS_PITCH]

    const int tid = threadIdx.x;
    const int bid = blockIdx.x;
    const int ug  = bid >> 2;                 // unit group 0..31
    const int ub  = ug * 16;
    const int rb  = (bid & 3) * 32;           // first batch row

    const int u    = tid & 15;
    const int q    = tid >> 4;
    const int r0   = q * 2;
    const int r1   = r0 + 1;
    const int ucol = ub + u;

    const float* hin  = g_h[t & 1];
    float*       hout = g_h[(t + 1) & 1];

    // ---- accumulators from xz + bias (DRAM stream; issue first) ----
    const float* xzrow0 = g_xz + ((size_t)t * BATCH + rb + r0) * GDIM;
    const float* xzrow1 = g_xz + ((size_t)t * BATCH + rb + r1) * GDIM;
    float4 accA, accB;
    accA.x = xzrow0[0 * UDIM + ucol] + blstm[0 * UDIM + ucol];
    accA.y = xzrow0[1 * UDIM + ucol] + blstm[1 * UDIM + ucol];
    accA.z = xzrow0[2 * UDIM + ucol] + blstm[2 * UDIM + ucol];
    accA.w = xzrow0[3 * UDIM + ucol] + blstm[3 * UDIM + ucol];
    accB.x = xzrow1[0 * UDIM + ucol] + blstm[0 * UDIM + ucol];
    accB.y = xzrow1[1 * UDIM + ucol] + blstm[1 * UDIM + ucol];
    accB.z = xzrow1[2 * UDIM + ucol] + blstm[2 * UDIM + ucol];
    accB.w = xzrow1[3 * UDIM + ucol] + blstm[3 * UDIM + ucol];

    // ---- stage packed W slice: 32768 floats, fully coalesced ----
    {
        const float4* wsrc = (const float4*)(g_wpack + (size_t)ug * 32768);
        float4*       wdst = (float4*)ws;
#pragma unroll
        for (int j = 0; j < 32; ++j)
            wdst[tid + 256 * j] = wsrc[tid + 256 * j];
    }
    // ---- stage h tile: 32 rows x 512 ----
#pragma unroll
    for (int j = 0; j < 16; ++j) {
        int idx = tid + 256 * j;              // 0..4095 float4 slots
        int row = idx >> 7;                   // 128 float4 per row
        int k4  = idx & 127;
        *(float4*)&hs[row * HS_PITCH + k4 * 4] =
            *(const float4*)(hin + (size_t)(rb + row) * UDIM + k4 * 4);
    }
    __syncthreads();

    // ---- dot products: k = 0..511 ----
    const float* hrow0 = &hs[r0 * HS_PITCH];
    const float* hrow1 = &hs[r1 * HS_PITCH];
    const float* wbase = &ws[u * 4];
#pragma unroll 4
    for (int k = 0; k < 512; k += 4) {
        float4 ha = *(const float4*)&hrow0[k];
        float4 hb = *(const float4*)&hrow1[k];
        float4 w0 = *(const float4*)&wbase[(k + 0) * 64];
        float4 w1 = *(const float4*)&wbase[(k + 1) * 64];
        float4 w2 = *(const float4*)&wbase[(k + 2) * 64];
        float4 w3 = *(const float4*)&wbase[(k + 3) * 64];
        accA.x = fmaf(ha.x, w0.x, accA.x); accB.x = fmaf(hb.x, w0.x, accB.x);
        accA.y = fmaf(ha.x, w0.y, accA.y); accB.y = fmaf(hb.x, w0.y, accB.y);
        accA.z = fmaf(ha.x, w0.z, accA.z); accB.z = fmaf(hb.x, w0.z, accB.z);
        accA.w = fmaf(ha.x, w0.w, accA.w); accB.w = fmaf(hb.x, w0.w, accB.w);
        accA.x = fmaf(ha.y, w1.x, accA.x); accB.x = fmaf(hb.y, w1.x, accB.x);
        accA.y = fmaf(ha.y, w1.y, accA.y); accB.y = fmaf(hb.y, w1.y, accB.y);
        accA.z = fmaf(ha.y, w1.z, accA.z); accB.z = fmaf(hb.y, w1.z, accB.z);
        accA.w = fmaf(ha.y, w1.w, accA.w); accB.w = fmaf(hb.y, w1.w, accB.w);
        accA.x = fmaf(ha.z, w2.x, accA.x); accB.x = fmaf(hb.z, w2.x, accB.x);
        accA.y = fmaf(ha.z, w2.y, accA.y); accB.y = fmaf(hb.z, w2.y, accB.y);
        accA.z = fmaf(ha.z, w2.z, accA.z); accB.z = fmaf(hb.z, w2.z, accB.z);
        accA.w = fmaf(ha.z, w2.w, accA.w); accB.w = fmaf(hb.z, w2.w, accB.w);
        accA.x = fmaf(ha.w, w3.x, accA.x); accB.x = fmaf(hb.w, w3.x, accB.x);
        accA.y = fmaf(ha.w, w3.y, accA.y); accB.y = fmaf(hb.w, w3.y, accB.y);
        accA.z = fmaf(ha.w, w3.z, accA.z); accB.z = fmaf(hb.w, w3.z, accB.z);
        accA.w = fmaf(ha.w, w3.w, accA.w); accB.w = fmaf(hb.w, w3.w, accB.w);
    }

    // ---- gate math; c in global (L2-resident, 512 KB) ----
    {
        int grow = rb + r0;
        float ig = 1.f / (1.f + __expf(-accA.x));
        float fg = 1.f / (1.f + __expf(-accA.y));
        float gg = tanhf(accA.z);
        float og = 1.f / (1.f + __expf(-accA.w));
        float cc = fg * g_c[(size_t)grow * UDIM + ucol] + ig * gg;
        g_c[(size_t)grow * UDIM + ucol] = cc;
        float h = og * tanhf(cc);
        hout[(size_t)grow * UDIM + ucol] = h;
        g_hseq[((size_t)t * BATCH + grow) * UDIM + ucol] = h * mask[t * BATCH + grow];
    }
    {
        int grow = rb + r1;
        float ig = 1.f / (1.f + __expf(-accB.x));
        float fg = 1.f / (1.f + __expf(-accB.y));
        float gg = tanhf(accB.z);
        float og = 1.f / (1.f + __expf(-accB.w));
        float cc = fg * g_c[(size_t)grow * UDIM + ucol] + ig * gg;
        g_c[(size_t)grow * UDIM + ucol] = cc;
        float h = og * tanhf(cc);
        hout[(size_t)grow * UDIM + ucol] = h;
        g_hseq[((size_t)t * BATCH + grow) * UDIM + ucol] = h * mask[t * BATCH + grow];
    }
}

// ---------------- row softmax in place (1024 cols, 1 block/row) -------------------
__global__ void __launch_bounds__(256) softmax_kernel(float* __restrict__ out) {
    const int row = blockIdx.x;
    float* p = out + (size_t)row * NCODES;
    const int tid = threadIdx.x;

    float4 v = *(float4*)(p + tid * 4);

    __shared__ float warpred[8];
    __shared__ float bcast;

    float m = fmaxf(fmaxf(v.x, v.y), fmaxf(v.z, v.w));
#pragma unroll
    for (int o = 16; o > 0; o >>= 1) m = fmaxf(m, __shfl_xor_sync(0xffffffffu, m, o));
    if ((tid & 31) == 0) warpred[tid >> 5] = m;
    __syncthreads();
    if (tid == 0) {
        float mm = warpred[0];
#pragma unroll
        for (int i = 1; i < 8; ++i) mm = fmaxf(mm, warpred[i]);
        bcast = mm;
    }
    __syncthreads();
    const float M = bcast;

    float4 e;
    e.x = __expf(v.x - M);
    e.y = __expf(v.y - M);
    e.z = __expf(v.z - M);
    e.w = __expf(v.w - M);
    float s = e.x + e.y + e.z + e.w;
#pragma unroll
    for (int o = 16; o > 0; o >>= 1) s += __shfl_xor_sync(0xffffffffu, s, o);
    if ((tid & 31) == 0) warpred[tid >> 5] = s;
    __syncthreads();
    if (tid == 0) {
        float ss = warpred[0];
#pragma unroll
        for (int i = 1; i < 8; ++i) ss += warpred[i];
        bcast = ss;
    }
    __syncthreads();
    const float inv = 1.f / bcast;

    e.x *= inv; e.y *= inv; e.z *= inv; e.w *= inv;
    *(float4*)(p + tid * 4) = e;
}

// ---------------- launch ----------------------------------------------------------
extern "C" void kernel_launch(void* const* d_in, const int* in_sizes, int n_in,
                              void* d_out, int out_size) {
    const float* x       = (const float*)d_in[0];  // [T,B,F]
    const float* mask    = (const float*)d_in[1];  // [T,B]
    const float* W_in    = (const float*)d_in[2];  // [F,4U]
    const float* W_rec   = (const float*)d_in[3];  // [U,4U]
    const float* b_lstm  = (const float*)d_in[4];  // [4U]
    const float* W_dense = (const float*)d_in[5];  // [U,CODES]
    const float* b_dense = (const float*)d_in[6];  // [CODES]
    float* out = (float*)d_out;                    // [T,B,CODES]

    float* xz   = nullptr;
    float* hseq = nullptr;
    cudaGetSymbolAddress((void**)&xz, g_xz);
    cudaGetSymbolAddress((void**)&hseq, g_hseq);

    const int rec_smem = (512 * 64 + 32 * HS_PITCH) * (int)sizeof(float); // 197120 B
    cudaFuncSetAttribute(lstm_step_kernel,
                         cudaFuncAttributeMaxDynamicSharedMemorySize, rec_smem);

    // 1) xz = x @ W_in + b_lstm   (M=32768, N=2048, K=1024)
    {
        dim3 grid(GDIM / 128, (T_STEPS * BATCH) / 128);
        sgemm_bias<false><<<grid, 256>>>(x, W_in, b_lstm, xz,
                                         T_STEPS * BATCH, GDIM, FDIM);
    }

    // 2) zero h/c state; pack W_rec
    init_state<<<(BATCH * UDIM + 255) / 256, 256>>>();
    pack_wrec<<<(UDIM * GDIM + 255) / 256, 256>>>(W_rec);

    // 3) recurrence: one launch per timestep (graph nodes; no device barrier)
    for (int t = 0; t < T_STEPS; ++t)
        lstm_step_kernel<<<128, 256, rec_smem>>>(t, b_lstm, mask);

    // 4) logits = relu(masked_hseq @ W_dense + b_dense)  (M=32768, N=1024, K=512)
    {
        dim3 grid(NCODES / 128, (T_STEPS * BATCH) / 128);
        sgemm_bias<true><<<grid, 256>>>(hseq, W_dense, b_dense, out,
                                        T_STEPS * BATCH, NCODES, UDIM);
    }

    // 5) softmax rows in place
    softmax_kernel<<<T_STEPS * BATCH, 256>>>(out);
}